// round 3
// baseline (speedup 1.0000x reference)
#include <cuda_runtime.h>
#include <cstdint>
#include <math.h>

// Problem constants
#define kD    1024          // d_model
#define kE    256           // e_dim
#define kNE   2048          // n_e
#define kCH   4
#define kM1   16384         // B*S rows for gemm1/gemm2
#define kMR   65536         // B*S*n_channel rows for distances

// -------- scratch (static device globals; no allocations) --------
__device__ float  g_cz[(size_t)kM1 * kD];          // 64 MB
__device__ float  g_logits[(size_t)kMR * kNE];     // 512 MB
__device__ float  g_esq[kNE];
__device__ float  g_czsq[kMR];
__device__ int    g_idx[kMR];
__device__ double g_part[4096];

// ------------------------- threefry2x32 (key = [0, 42]) -------------------------
__device__ __forceinline__ uint32_t rotl32(uint32_t x, int r) { return (x << r) | (x >> (32 - r)); }

__device__ __forceinline__ void threefry2x32_42(uint32_t x0, uint32_t x1,
                                                uint32_t& o0, uint32_t& o1) {
    const uint32_t ks0 = 0u, ks1 = 42u;
    const uint32_t ks2 = 0x1BD11BDAu ^ ks0 ^ ks1;
    x0 += ks0; x1 += ks1;
#define TF_R(r) { x0 += x1; x1 = rotl32(x1, (r)); x1 ^= x0; }
    TF_R(13) TF_R(15) TF_R(26) TF_R(6)
    x0 += ks1; x1 += ks2 + 1u;
    TF_R(17) TF_R(29) TF_R(16) TF_R(24)
    x0 += ks2; x1 += ks0 + 2u;
    TF_R(13) TF_R(15) TF_R(26) TF_R(6)
    x0 += ks0; x1 += ks1 + 3u;
    TF_R(17) TF_R(29) TF_R(16) TF_R(24)
    x0 += ks1; x1 += ks2 + 4u;
    TF_R(13) TF_R(15) TF_R(26) TF_R(6)
    x0 += ks2; x1 += ks0 + 5u;
#undef TF_R
    o0 = x0; o1 = x1;
}

// gumbel value for flat element j of the (65536, 2048) noise tensor.
// JAX with jax_threefry_partitionable=True (default in modern JAX):
//   counter for element j (uint64 flat index) = (hi32(j), lo32(j)) = (0, j)
//   32-bit output = out0 ^ out1
__device__ __forceinline__ float gumbel_at(uint32_t j) {
    uint32_t r0, r1;
    threefry2x32_42(0u, j, r0, r1);
    uint32_t bits = r0 ^ r1;
    float f = __uint_as_float((bits >> 9) | 0x3f800000u) - 1.0f;
    const float TINY = 1.17549435e-38f;
    float u = fmaxf(TINY, f + TINY);   // matches max(tiny, f*(1-tiny)+tiny) in fp32
    return -logf(-logf(u));
}

// ------------------------- SGEMM: C = A(MxK) @ B(KxN) + bias -------------------------
// GATHER=1: A(m,k) = Etab[ gidx[m*4 + (k>>8)]*256 + (k&255) ]; scalar epilogue stores
//           (C may be only 4-byte aligned: z_q lives at out+1 after the loss scalar).
template <int GATHER>
__global__ void __launch_bounds__(256)
sgemm_kernel(const float* __restrict__ A, const float* __restrict__ Bm,
             const float* __restrict__ bias, float* __restrict__ C,
             int M, int N, int K,
             const int* __restrict__ gidx, const float* __restrict__ Etab) {
    __shared__ float As[16][132];
    __shared__ float Bs[16][132];
    const int tid = threadIdx.x;
    const int bx = blockIdx.x, by = blockIdx.y;
    const int tx = tid & 15, ty = tid >> 4;

    const int ar = tid >> 2;            // 0..63
    const int ac = (tid & 3) << 2;      // 0,4,8,12
    const int br = tid >> 5;            // 0..7
    const int bc = (tid & 31) << 2;     // 0..124

    float acc[8][8];
#pragma unroll
    for (int i = 0; i < 8; i++)
#pragma unroll
        for (int j = 0; j < 8; j++) acc[i][j] = 0.0f;

    for (int k0 = 0; k0 < K; k0 += 16) {
#pragma unroll
        for (int h = 0; h < 2; h++) {
            int row = by * 128 + ar + h * 64;
            float4 v;
            if (GATHER) {
                int k = k0 + ac;
                int code = gidx[row * kCH + (k >> 8)];
                v = *reinterpret_cast<const float4*>(&Etab[(size_t)code * kE + (k & 255)]);
            } else {
                v = *reinterpret_cast<const float4*>(&A[(size_t)row * K + k0 + ac]);
            }
            As[ac + 0][ar + h * 64] = v.x;
            As[ac + 1][ar + h * 64] = v.y;
            As[ac + 2][ar + h * 64] = v.z;
            As[ac + 3][ar + h * 64] = v.w;
        }
#pragma unroll
        for (int h = 0; h < 2; h++) {
            int krow = k0 + br + h * 8;
            float4 v = *reinterpret_cast<const float4*>(&Bm[(size_t)krow * N + bx * 128 + bc]);
            Bs[br + h * 8][bc + 0] = v.x;
            Bs[br + h * 8][bc + 1] = v.y;
            Bs[br + h * 8][bc + 2] = v.z;
            Bs[br + h * 8][bc + 3] = v.w;
        }
        __syncthreads();
#pragma unroll
        for (int kk = 0; kk < 16; kk++) {
            float a[8], b[8];
#pragma unroll
            for (int i = 0; i < 8; i++) a[i] = As[kk][ty * 8 + i];
#pragma unroll
            for (int j = 0; j < 8; j++) b[j] = Bs[kk][tx * 8 + j];
#pragma unroll
            for (int i = 0; i < 8; i++)
#pragma unroll
                for (int j = 0; j < 8; j++) acc[i][j] = fmaf(a[i], b[j], acc[i][j]);
        }
        __syncthreads();
    }

#pragma unroll
    for (int i = 0; i < 8; i++) {
        int row = by * 128 + ty * 8 + i;
        if (GATHER) {
            // scalar stores: C may be misaligned for float4 (out + 1)
#pragma unroll
            for (int j = 0; j < 8; j++) {
                int col = bx * 128 + tx * 8 + j;
                C[(size_t)row * N + col] = acc[i][j] + bias[col];
            }
        } else {
#pragma unroll
            for (int j = 0; j < 8; j += 4) {
                int col = bx * 128 + tx * 8 + j;
                float4 v;
                v.x = acc[i][j + 0] + bias[col + 0];
                v.y = acc[i][j + 1] + bias[col + 1];
                v.z = acc[i][j + 2] + bias[col + 2];
                v.w = acc[i][j + 3] + bias[col + 3];
                *reinterpret_cast<float4*>(&C[(size_t)row * N + col]) = v;
            }
        }
    }
}

// ------------------------- distance GEMM: logits = (czsq+esq) - 2*cz.E -------------------------
__global__ void __launch_bounds__(256)
dist_kernel(const float* __restrict__ cz, const float* __restrict__ E,
            const float* __restrict__ czsq, const float* __restrict__ esq,
            float* __restrict__ logits) {
    __shared__ float As[16][132];
    __shared__ float Bs[16][132];
    const int tid = threadIdx.x;
    const int bx = blockIdx.x, by = blockIdx.y;   // bx: code tile (16), by: row tile (512)
    const int tx = tid & 15, ty = tid >> 4;

    const int ar = tid >> 2;
    const int ac = (tid & 3) << 2;

    float acc[8][8];
#pragma unroll
    for (int i = 0; i < 8; i++)
#pragma unroll
        for (int j = 0; j < 8; j++) acc[i][j] = 0.0f;

    for (int k0 = 0; k0 < kE; k0 += 16) {
#pragma unroll
        for (int h = 0; h < 2; h++) {
            int row = by * 128 + ar + h * 64;
            float4 v = *reinterpret_cast<const float4*>(&cz[(size_t)row * kE + k0 + ac]);
            As[ac + 0][ar + h * 64] = v.x;
            As[ac + 1][ar + h * 64] = v.y;
            As[ac + 2][ar + h * 64] = v.z;
            As[ac + 3][ar + h * 64] = v.w;
        }
#pragma unroll
        for (int h = 0; h < 2; h++) {
            int code = bx * 128 + ar + h * 64;
            float4 v = *reinterpret_cast<const float4*>(&E[(size_t)code * kE + k0 + ac]);
            Bs[ac + 0][ar + h * 64] = v.x;
            Bs[ac + 1][ar + h * 64] = v.y;
            Bs[ac + 2][ar + h * 64] = v.z;
            Bs[ac + 3][ar + h * 64] = v.w;
        }
        __syncthreads();
#pragma unroll
        for (int kk = 0; kk < 16; kk++) {
            float a[8], b[8];
#pragma unroll
            for (int i = 0; i < 8; i++) a[i] = As[kk][ty * 8 + i];
#pragma unroll
            for (int j = 0; j < 8; j++) b[j] = Bs[kk][tx * 8 + j];
#pragma unroll
            for (int i = 0; i < 8; i++)
#pragma unroll
                for (int j = 0; j < 8; j++) acc[i][j] = fmaf(a[i], b[j], acc[i][j]);
        }
        __syncthreads();
    }

#pragma unroll
    for (int i = 0; i < 8; i++) {
        int row = by * 128 + ty * 8 + i;
        float cs = czsq[row];
#pragma unroll
        for (int j = 0; j < 8; j += 4) {
            int col = bx * 128 + tx * 8 + j;
            float4 v;
            // replicate reference rounding: fl( fl(czsq + esq) - fl(2*dot) )
            v.x = (cs + esq[col + 0]) - 2.0f * acc[i][j + 0];
            v.y = (cs + esq[col + 1]) - 2.0f * acc[i][j + 1];
            v.z = (cs + esq[col + 2]) - 2.0f * acc[i][j + 2];
            v.w = (cs + esq[col + 3]) - 2.0f * acc[i][j + 3];
            *reinterpret_cast<float4*>(&logits[(size_t)row * kNE + col]) = v;
        }
    }
}

// ------------------------- row squared norms (double accumulate) -------------------------
__global__ void rowsq_kernel(const float* __restrict__ X, float* __restrict__ out, int ncols4) {
    // one warp per row of 256 floats (ncols4 = 64 float4s)
    int row = blockIdx.x * 8 + (threadIdx.x >> 5);
    int lane = threadIdx.x & 31;
    const float4* p = reinterpret_cast<const float4*>(X + (size_t)row * (ncols4 * 4));
    double s = 0.0;
    for (int i = lane; i < ncols4; i += 32) {
        float4 v = p[i];
        s += (double)v.x * v.x + (double)v.y * v.y + (double)v.z * v.z + (double)v.w * v.w;
    }
#pragma unroll
    for (int o = 16; o > 0; o >>= 1) s += __shfl_xor_sync(0xffffffffu, s, o);
    if (lane == 0) out[row] = (float)s;
}

// ------------------------- per-row max + gumbel argmax -------------------------
__global__ void __launch_bounds__(128)
argmax_kernel(const float* __restrict__ logits, int* __restrict__ outidx) {
    int row = blockIdx.x;
    const float* lr = logits + (size_t)row * kNE;
    int t = threadIdx.x;

    float lv[16];
    float mx = -INFINITY;
#pragma unroll
    for (int i = 0; i < 16; i++) {
        lv[i] = lr[i * 128 + t];
        mx = fmaxf(mx, lv[i]);
    }
    __shared__ float sMax[128];
    sMax[t] = mx;
    __syncthreads();
    for (int o = 64; o > 0; o >>= 1) {
        if (t < o) sMax[t] = fmaxf(sMax[t], sMax[t + o]);
        __syncthreads();
    }
    float rowmax = sMax[0];
    __syncthreads();

    float best = -INFINITY;
    int bi = kNE;
    uint32_t base = (uint32_t)row * (uint32_t)kNE;
#pragma unroll
    for (int i = 0; i < 16; i++) {
        int e = i * 128 + t;
        float g = gumbel_at(base + (uint32_t)e);
        float s = (lv[i] - rowmax) + g;  // fl of exact diff + gumbel, matches argmax(g + l')
        if (s > best || (s == best && e < bi)) { best = s; bi = e; }
    }
    __shared__ float sBv[128];
    __shared__ int sBi[128];
    sBv[t] = best; sBi[t] = bi;
    __syncthreads();
    for (int o = 64; o > 0; o >>= 1) {
        if (t < o) {
            if (sBv[t + o] > sBv[t] || (sBv[t + o] == sBv[t] && sBi[t + o] < sBi[t])) {
                sBv[t] = sBv[t + o]; sBi[t] = sBi[t + o];
            }
        }
        __syncthreads();
    }
    if (t == 0) outidx[row] = sBi[0];
}

// ------------------------- loss partials: sum (E[idx]-cz)^2 -------------------------
__global__ void __launch_bounds__(256)
loss_kernel(const float* __restrict__ cz, const int* __restrict__ idx,
            const float* __restrict__ E, double* __restrict__ part) {
    double s = 0.0;
    size_t blockBase = (size_t)blockIdx.x * 4096;
#pragma unroll
    for (int i = 0; i < 16; i++) {
        size_t g = blockBase + (size_t)i * 256 + threadIdx.x;
        int rowr = (int)(g >> 8);
        int pos = (int)(g & 255);
        float d = E[(size_t)idx[rowr] * kE + pos] - cz[g];
        s += (double)d * d;
    }
    __shared__ double sd[256];
    sd[threadIdx.x] = s;
    __syncthreads();
    for (int o = 128; o > 0; o >>= 1) {
        if (threadIdx.x < o) sd[threadIdx.x] += sd[threadIdx.x + o];
        __syncthreads();
    }
    if (threadIdx.x == 0) part[blockIdx.x] = sd[0];
}

__global__ void loss_final_kernel(const double* __restrict__ part, float* __restrict__ out) {
    double s = 0.0;
    for (int i = threadIdx.x; i < 4096; i += 256) s += part[i];
    __shared__ double sd[256];
    sd[threadIdx.x] = s;
    __syncthreads();
    for (int o = 128; o > 0; o >>= 1) {
        if (threadIdx.x < o) sd[threadIdx.x] += sd[threadIdx.x + o];
        __syncthreads();
    }
    if (threadIdx.x == 0) {
        float m = (float)(sd[0] / 16777216.0);
        out[0] = m + 0.25f * m;    // mean1 + BETA*mean2, numerically identical means
    }
}

// ------------------------- launch -------------------------
extern "C" void kernel_launch(void* const* d_in, const int* in_sizes, int n_in,
                              void* d_out, int out_size) {
    const float* z  = (const float*)d_in[0];
    const float* W0 = (const float*)d_in[1];
    const float* b0 = (const float*)d_in[2];
    const float* W1 = (const float*)d_in[3];
    const float* b1 = (const float*)d_in[4];
    const float* E  = (const float*)d_in[5];
    float* out = (float*)d_out;

    float *p_cz, *p_logits, *p_esq, *p_czsq;
    int* p_idx;
    double* p_part;
    cudaGetSymbolAddress((void**)&p_cz, g_cz);
    cudaGetSymbolAddress((void**)&p_logits, g_logits);
    cudaGetSymbolAddress((void**)&p_esq, g_esq);
    cudaGetSymbolAddress((void**)&p_czsq, g_czsq);
    cudaGetSymbolAddress((void**)&p_idx, g_idx);
    cudaGetSymbolAddress((void**)&p_part, g_part);

    // 1) cz = z @ W0 + b0
    sgemm_kernel<0><<<dim3(kD / 128, kM1 / 128), 256>>>(z, W0, b0, p_cz, kM1, kD, kD,
                                                        nullptr, nullptr);
    // 2) row squared norms
    rowsq_kernel<<<kNE / 8, 256>>>(E, p_esq, kE / 4);
    rowsq_kernel<<<kMR / 8, 256>>>(p_cz, p_czsq, kE / 4);
    // 3) logits
    dist_kernel<<<dim3(kNE / 128, kMR / 128), 256>>>(p_cz, E, p_czsq, p_esq, p_logits);
    // 4) categorical sample (rowmax + threefry gumbel + argmax)
    argmax_kernel<<<kMR, 128>>>(p_logits, p_idx);

    int zoff = out_size - kM1 * kD;   // layout: [loss?][z_q]
    if (zoff >= 1) {
        // 5) loss
        loss_kernel<<<4096, 256>>>(p_cz, p_idx, E, p_part);
        loss_final_kernel<<<1, 256>>>(p_part, out);
    }
    if (out_size >= kM1 * kD) {
        // 6) z_q = gather(E, idx) @ W1 + b1
        float* zq = out + (zoff > 0 ? zoff : 0);
        sgemm_kernel<1><<<dim3(kD / 128, kM1 / 128), 256>>>(nullptr, W1, b1, zq, kM1, kD, kD,
                                                            p_idx, E);
    }
}

// round 4
// speedup vs baseline: 1.2846x; 1.2846x over previous
#include <cuda_runtime.h>
#include <cstdint>
#include <math.h>

// Problem constants
#define kD    1024          // d_model
#define kE    256           // e_dim
#define kNE   2048          // n_e
#define kCH   4
#define kM1   16384         // B*S rows
#define kMR   65536         // B*S*n_channel rows

// -------- scratch (static device globals; no allocations) --------
__device__ float  g_cz[(size_t)kM1 * kD];          // 64 MB
__device__ float  g_logits[(size_t)kMR * kNE];     // 512 MB
__device__ float  g_P[(size_t)kCH * kNE * kD];     // 32 MB  (E @ W1 per channel)
__device__ float  g_esq[kNE];
__device__ float  g_czsq[kMR];
__device__ int    g_idx[kMR];
__device__ double g_part[4096];

// ------------------------- f32x2 packed FMA helpers -------------------------
#define FFMA2(d, a, b) asm("fma.rn.f32x2 %0, %1, %2, %0;" : "+l"(d) : "l"(a), "l"(b))
#define PACK2(d, f)    asm("mov.b64 %0, {%1, %1};" : "=l"(d) : "r"(__float_as_uint(f)))
#define UNPACK2(lo, hi, d) asm("mov.b64 {%0, %1}, %2;" : "=r"(lo), "=r"(hi) : "l"(d))

// ------------------------- threefry2x32 (key = [0, 42]) -------------------------
__device__ __forceinline__ uint32_t rotl32(uint32_t x, int r) { return (x << r) | (x >> (32 - r)); }

__device__ __forceinline__ void threefry2x32_42(uint32_t x0, uint32_t x1,
                                                uint32_t& o0, uint32_t& o1) {
    const uint32_t ks0 = 0u, ks1 = 42u;
    const uint32_t ks2 = 0x1BD11BDAu ^ ks0 ^ ks1;
    x0 += ks0; x1 += ks1;
#define TF_R(r) { x0 += x1; x1 = rotl32(x1, (r)); x1 ^= x0; }
    TF_R(13) TF_R(15) TF_R(26) TF_R(6)
    x0 += ks1; x1 += ks2 + 1u;
    TF_R(17) TF_R(29) TF_R(16) TF_R(24)
    x0 += ks2; x1 += ks0 + 2u;
    TF_R(13) TF_R(15) TF_R(26) TF_R(6)
    x0 += ks0; x1 += ks1 + 3u;
    TF_R(17) TF_R(29) TF_R(16) TF_R(24)
    x0 += ks1; x1 += ks2 + 4u;
    TF_R(13) TF_R(15) TF_R(26) TF_R(6)
    x0 += ks2; x1 += ks0 + 5u;
#undef TF_R
    o0 = x0; o1 = x1;
}

// uniform u for flat element j (partitionable threefry: counter (0, j), out = r0^r1)
__device__ __forceinline__ float uniform_at(uint32_t j) {
    uint32_t r0, r1;
    threefry2x32_42(0u, j, r0, r1);
    uint32_t bits = r0 ^ r1;
    float f = __uint_as_float((bits >> 9) | 0x3f800000u) - 1.0f;
    const float TINY = 1.17549435e-38f;
    return fmaxf(TINY, f + TINY);
}
__device__ __forceinline__ float gumbel_of_u(float u) { return -logf(-logf(u)); }

// ======================= GEMM0: cz = z @ W0 + b0 (f32x2, double-buffered) =======================
// M=16384, N=1024, K=1024. Block tile 128x128x16, 256 threads, 8x8 microtile.
__global__ void __launch_bounds__(256)
gemm0_kernel(const float* __restrict__ A, const float* __restrict__ Bm,
             const float* __restrict__ bias, float* __restrict__ C, int N, int K) {
    __shared__ float As[2][16][132];
    __shared__ float Bs[2][16][132];
    const int tid = threadIdx.x;
    const int bx = blockIdx.x, by = blockIdx.y;
    const int tx = tid & 15, ty = tid >> 4;

    const int ar = tid >> 2, ac = (tid & 3) << 2;   // A loader
    const int br = tid >> 5, bc = (tid & 31) << 2;  // B loader

    unsigned long long acc2[8][4];
#pragma unroll
    for (int i = 0; i < 8; i++)
#pragma unroll
        for (int j = 0; j < 4; j++) acc2[i][j] = 0ull;

    const int S = K / 16;
    float4 a4[2], b4[2];

    // prefetch stage 0
#pragma unroll
    for (int h = 0; h < 2; h++) {
        a4[h] = *reinterpret_cast<const float4*>(&A[(size_t)(by * 128 + ar + h * 64) * K + ac]);
        b4[h] = *reinterpret_cast<const float4*>(&Bm[(size_t)(br + h * 8) * N + bx * 128 + bc]);
    }
    {
        int buf = 0;
#pragma unroll
        for (int h = 0; h < 2; h++) {
            As[buf][ac + 0][ar + h * 64] = a4[h].x;
            As[buf][ac + 1][ar + h * 64] = a4[h].y;
            As[buf][ac + 2][ar + h * 64] = a4[h].z;
            As[buf][ac + 3][ar + h * 64] = a4[h].w;
            *reinterpret_cast<float4*>(&Bs[buf][br + h * 8][bc]) = b4[h];
        }
    }
    __syncthreads();

    for (int s = 0; s < S; s++) {
        const int cur = s & 1;
        if (s + 1 < S) {
            int k1 = (s + 1) * 16;
#pragma unroll
            for (int h = 0; h < 2; h++) {
                a4[h] = *reinterpret_cast<const float4*>(&A[(size_t)(by * 128 + ar + h * 64) * K + k1 + ac]);
                b4[h] = *reinterpret_cast<const float4*>(&Bm[(size_t)(k1 + br + h * 8) * N + bx * 128 + bc]);
            }
        }
#pragma unroll
        for (int kk = 0; kk < 16; kk++) {
            float4 av0 = *reinterpret_cast<const float4*>(&As[cur][kk][ty * 8]);
            float4 av1 = *reinterpret_cast<const float4*>(&As[cur][kk][ty * 8 + 4]);
            const unsigned long long* bp =
                reinterpret_cast<const unsigned long long*>(&Bs[cur][kk][tx * 8]);
            unsigned long long b2[4];
#pragma unroll
            for (int j = 0; j < 4; j++) b2[j] = bp[j];
            unsigned long long ap[8];
            PACK2(ap[0], av0.x); PACK2(ap[1], av0.y); PACK2(ap[2], av0.z); PACK2(ap[3], av0.w);
            PACK2(ap[4], av1.x); PACK2(ap[5], av1.y); PACK2(ap[6], av1.z); PACK2(ap[7], av1.w);
#pragma unroll
            for (int i = 0; i < 8; i++)
#pragma unroll
                for (int j = 0; j < 4; j++) FFMA2(acc2[i][j], ap[i], b2[j]);
        }
        if (s + 1 < S) {
            int nb = (s + 1) & 1;
#pragma unroll
            for (int h = 0; h < 2; h++) {
                As[nb][ac + 0][ar + h * 64] = a4[h].x;
                As[nb][ac + 1][ar + h * 64] = a4[h].y;
                As[nb][ac + 2][ar + h * 64] = a4[h].z;
                As[nb][ac + 3][ar + h * 64] = a4[h].w;
                *reinterpret_cast<float4*>(&Bs[nb][br + h * 8][bc]) = b4[h];
            }
        }
        __syncthreads();
    }

#pragma unroll
    for (int i = 0; i < 8; i++) {
        int row = by * 128 + ty * 8 + i;
        int col = bx * 128 + tx * 8;
        float a[8];
#pragma unroll
        for (int j = 0; j < 4; j++) {
            uint32_t lo, hi;
            UNPACK2(lo, hi, acc2[i][j]);
            a[2 * j] = __uint_as_float(lo);
            a[2 * j + 1] = __uint_as_float(hi);
        }
#pragma unroll
        for (int j = 0; j < 8; j += 4) {
            float4 v;
            v.x = a[j + 0] + bias[col + j + 0];
            v.y = a[j + 1] + bias[col + j + 1];
            v.z = a[j + 2] + bias[col + j + 2];
            v.w = a[j + 3] + bias[col + j + 3];
            *reinterpret_cast<float4*>(&C[(size_t)row * N + col + j]) = v;
        }
    }
}

// ======================= dist: logits = (czsq+esq) - 2*cz.E (f32x2, dbuf) =======================
__global__ void __launch_bounds__(256)
dist_kernel(const float* __restrict__ cz, const float* __restrict__ E,
            const float* __restrict__ czsq, const float* __restrict__ esq,
            float* __restrict__ logits) {
    __shared__ float As[2][16][132];
    __shared__ float Bs[2][16][132];
    const int tid = threadIdx.x;
    const int bx = blockIdx.x, by = blockIdx.y;
    const int tx = tid & 15, ty = tid >> 4;

    const int ar = tid >> 2, ac = (tid & 3) << 2;

    unsigned long long acc2[8][4];
#pragma unroll
    for (int i = 0; i < 8; i++)
#pragma unroll
        for (int j = 0; j < 4; j++) acc2[i][j] = 0ull;

    const int S = kE / 16;   // 16 stages
    float4 a4[2], b4[2];

#pragma unroll
    for (int h = 0; h < 2; h++) {
        a4[h] = *reinterpret_cast<const float4*>(&cz[(size_t)(by * 128 + ar + h * 64) * kE + ac]);
        b4[h] = *reinterpret_cast<const float4*>(&E[(size_t)(bx * 128 + ar + h * 64) * kE + ac]);
    }
    {
        int buf = 0;
#pragma unroll
        for (int h = 0; h < 2; h++) {
            As[buf][ac + 0][ar + h * 64] = a4[h].x;
            As[buf][ac + 1][ar + h * 64] = a4[h].y;
            As[buf][ac + 2][ar + h * 64] = a4[h].z;
            As[buf][ac + 3][ar + h * 64] = a4[h].w;
            Bs[buf][ac + 0][ar + h * 64] = b4[h].x;
            Bs[buf][ac + 1][ar + h * 64] = b4[h].y;
            Bs[buf][ac + 2][ar + h * 64] = b4[h].z;
            Bs[buf][ac + 3][ar + h * 64] = b4[h].w;
        }
    }
    __syncthreads();

    for (int s = 0; s < S; s++) {
        const int cur = s & 1;
        if (s + 1 < S) {
            int k1 = (s + 1) * 16;
#pragma unroll
            for (int h = 0; h < 2; h++) {
                a4[h] = *reinterpret_cast<const float4*>(&cz[(size_t)(by * 128 + ar + h * 64) * kE + k1 + ac]);
                b4[h] = *reinterpret_cast<const float4*>(&E[(size_t)(bx * 128 + ar + h * 64) * kE + k1 + ac]);
            }
        }
#pragma unroll
        for (int kk = 0; kk < 16; kk++) {
            float4 av0 = *reinterpret_cast<const float4*>(&As[cur][kk][ty * 8]);
            float4 av1 = *reinterpret_cast<const float4*>(&As[cur][kk][ty * 8 + 4]);
            const unsigned long long* bp =
                reinterpret_cast<const unsigned long long*>(&Bs[cur][kk][tx * 8]);
            unsigned long long b2[4];
#pragma unroll
            for (int j = 0; j < 4; j++) b2[j] = bp[j];
            unsigned long long ap[8];
            PACK2(ap[0], av0.x); PACK2(ap[1], av0.y); PACK2(ap[2], av0.z); PACK2(ap[3], av0.w);
            PACK2(ap[4], av1.x); PACK2(ap[5], av1.y); PACK2(ap[6], av1.z); PACK2(ap[7], av1.w);
#pragma unroll
            for (int i = 0; i < 8; i++)
#pragma unroll
                for (int j = 0; j < 4; j++) FFMA2(acc2[i][j], ap[i], b2[j]);
        }
        if (s + 1 < S) {
            int nb = (s + 1) & 1;
#pragma unroll
            for (int h = 0; h < 2; h++) {
                As[nb][ac + 0][ar + h * 64] = a4[h].x;
                As[nb][ac + 1][ar + h * 64] = a4[h].y;
                As[nb][ac + 2][ar + h * 64] = a4[h].z;
                As[nb][ac + 3][ar + h * 64] = a4[h].w;
                Bs[nb][ac + 0][ar + h * 64] = b4[h].x;
                Bs[nb][ac + 1][ar + h * 64] = b4[h].y;
                Bs[nb][ac + 2][ar + h * 64] = b4[h].z;
                Bs[nb][ac + 3][ar + h * 64] = b4[h].w;
            }
        }
        __syncthreads();
    }

#pragma unroll
    for (int i = 0; i < 8; i++) {
        int row = by * 128 + ty * 8 + i;
        int col = bx * 128 + tx * 8;
        float cs = czsq[row];
        float a[8];
#pragma unroll
        for (int j = 0; j < 4; j++) {
            uint32_t lo, hi;
            UNPACK2(lo, hi, acc2[i][j]);
            a[2 * j] = __uint_as_float(lo);
            a[2 * j + 1] = __uint_as_float(hi);
        }
#pragma unroll
        for (int j = 0; j < 8; j += 4) {
            float4 v;
            v.x = (cs + esq[col + j + 0]) - 2.0f * a[j + 0];
            v.y = (cs + esq[col + j + 1]) - 2.0f * a[j + 1];
            v.z = (cs + esq[col + j + 2]) - 2.0f * a[j + 2];
            v.w = (cs + esq[col + j + 3]) - 2.0f * a[j + 3];
            *reinterpret_cast<float4*>(&logits[(size_t)row * kNE + col + j]) = v;
        }
    }
}

// ======================= P = E @ W1_ch (per channel z) =======================
// M=2048, N=1024, K=256; grid (N/128, M/128, 4)
__global__ void __launch_bounds__(256)
pgemm_kernel(const float* __restrict__ E, const float* __restrict__ W1,
             float* __restrict__ P) {
    __shared__ float As[2][16][132];
    __shared__ float Bs[2][16][132];
    const int tid = threadIdx.x;
    const int bx = blockIdx.x, by = blockIdx.y, ch = blockIdx.z;
    const int tx = tid & 15, ty = tid >> 4;

    const int ar = tid >> 2, ac = (tid & 3) << 2;
    const int br = tid >> 5, bc = (tid & 31) << 2;

    const float* Bm = W1 + (size_t)ch * kE * kD;   // rows ch*256 .. +255

    unsigned long long acc2[8][4];
#pragma unroll
    for (int i = 0; i < 8; i++)
#pragma unroll
        for (int j = 0; j < 4; j++) acc2[i][j] = 0ull;

    const int S = kE / 16;
    float4 a4[2], b4[2];
#pragma unroll
    for (int h = 0; h < 2; h++) {
        a4[h] = *reinterpret_cast<const float4*>(&E[(size_t)(by * 128 + ar + h * 64) * kE + ac]);
        b4[h] = *reinterpret_cast<const float4*>(&Bm[(size_t)(br + h * 8) * kD + bx * 128 + bc]);
    }
    {
#pragma unroll
        for (int h = 0; h < 2; h++) {
            As[0][ac + 0][ar + h * 64] = a4[h].x;
            As[0][ac + 1][ar + h * 64] = a4[h].y;
            As[0][ac + 2][ar + h * 64] = a4[h].z;
            As[0][ac + 3][ar + h * 64] = a4[h].w;
            *reinterpret_cast<float4*>(&Bs[0][br + h * 8][bc]) = b4[h];
        }
    }
    __syncthreads();

    for (int s = 0; s < S; s++) {
        const int cur = s & 1;
        if (s + 1 < S) {
            int k1 = (s + 1) * 16;
#pragma unroll
            for (int h = 0; h < 2; h++) {
                a4[h] = *reinterpret_cast<const float4*>(&E[(size_t)(by * 128 + ar + h * 64) * kE + k1 + ac]);
                b4[h] = *reinterpret_cast<const float4*>(&Bm[(size_t)(k1 + br + h * 8) * kD + bx * 128 + bc]);
            }
        }
#pragma unroll
        for (int kk = 0; kk < 16; kk++) {
            float4 av0 = *reinterpret_cast<const float4*>(&As[cur][kk][ty * 8]);
            float4 av1 = *reinterpret_cast<const float4*>(&As[cur][kk][ty * 8 + 4]);
            const unsigned long long* bp =
                reinterpret_cast<const unsigned long long*>(&Bs[cur][kk][tx * 8]);
            unsigned long long b2[4];
#pragma unroll
            for (int j = 0; j < 4; j++) b2[j] = bp[j];
            unsigned long long ap[8];
            PACK2(ap[0], av0.x); PACK2(ap[1], av0.y); PACK2(ap[2], av0.z); PACK2(ap[3], av0.w);
            PACK2(ap[4], av1.x); PACK2(ap[5], av1.y); PACK2(ap[6], av1.z); PACK2(ap[7], av1.w);
#pragma unroll
            for (int i = 0; i < 8; i++)
#pragma unroll
                for (int j = 0; j < 4; j++) FFMA2(acc2[i][j], ap[i], b2[j]);
        }
        if (s + 1 < S) {
            int nb = (s + 1) & 1;
#pragma unroll
            for (int h = 0; h < 2; h++) {
                As[nb][ac + 0][ar + h * 64] = a4[h].x;
                As[nb][ac + 1][ar + h * 64] = a4[h].y;
                As[nb][ac + 2][ar + h * 64] = a4[h].z;
                As[nb][ac + 3][ar + h * 64] = a4[h].w;
                *reinterpret_cast<float4*>(&Bs[nb][br + h * 8][bc]) = b4[h];
            }
        }
        __syncthreads();
    }

    float* Pout = P + (size_t)ch * kNE * kD;
#pragma unroll
    for (int i = 0; i < 8; i++) {
        int row = by * 128 + ty * 8 + i;
        int col = bx * 128 + tx * 8;
#pragma unroll
        for (int j = 0; j < 4; j++) {
            uint32_t lo, hi;
            UNPACK2(lo, hi, acc2[i][j]);
            float2 v;
            v.x = __uint_as_float(lo);
            v.y = __uint_as_float(hi);
            *reinterpret_cast<float2*>(&Pout[(size_t)row * kD + col + 2 * j]) = v;
        }
    }
}

// ======================= z_q gather: out[m] = sum_ch P[ch][idx[m,ch]] + b1 =======================
__global__ void __launch_bounds__(256)
gather_zq_kernel(const float* __restrict__ P, const int* __restrict__ idx,
                 const float* __restrict__ b1, float* __restrict__ out) {
    int m = blockIdx.x;
    int c = threadIdx.x * 4;
    int4 id = *reinterpret_cast<const int4*>(&idx[m * 4]);
    float4 p0 = *reinterpret_cast<const float4*>(&P[((size_t)0 * kNE + id.x) * kD + c]);
    float4 p1 = *reinterpret_cast<const float4*>(&P[((size_t)1 * kNE + id.y) * kD + c]);
    float4 p2 = *reinterpret_cast<const float4*>(&P[((size_t)2 * kNE + id.z) * kD + c]);
    float4 p3 = *reinterpret_cast<const float4*>(&P[((size_t)3 * kNE + id.w) * kD + c]);
    float4 bb = *reinterpret_cast<const float4*>(&b1[c]);
    float4 v;
    v.x = ((p0.x + p1.x) + p2.x) + p3.x + bb.x;
    v.y = ((p0.y + p1.y) + p2.y) + p3.y + bb.y;
    v.z = ((p0.z + p1.z) + p2.z) + p3.z + bb.z;
    v.w = ((p0.w + p1.w) + p2.w) + p3.w + bb.w;
    size_t o = (size_t)m * kD + c;
    out[o + 0] = v.x; out[o + 1] = v.y; out[o + 2] = v.z; out[o + 3] = v.w;  // out may be +1 misaligned
}

// ------------------------- row squared norms (double accumulate) -------------------------
__global__ void rowsq_kernel(const float* __restrict__ X, float* __restrict__ out, int ncols4) {
    int row = blockIdx.x * 8 + (threadIdx.x >> 5);
    int lane = threadIdx.x & 31;
    const float4* p = reinterpret_cast<const float4*>(X + (size_t)row * (ncols4 * 4));
    double s = 0.0;
    for (int i = lane; i < ncols4; i += 32) {
        float4 v = p[i];
        s += (double)v.x * v.x + (double)v.y * v.y + (double)v.z * v.z + (double)v.w * v.w;
    }
#pragma unroll
    for (int o = 16; o > 0; o >>= 1) s += __shfl_xor_sync(0xffffffffu, s, o);
    if (lane == 0) out[row] = (float)s;
}

// ------------------------- pruned gumbel argmax -------------------------
// Sound pruning: score = (lv - rowmax) + g, (lv - rowmax) in [-D, 0], g monotone in u.
// Winner score >= g_top - D, so any code with g < g_top - D cannot win.
__global__ void __launch_bounds__(128)
argmax_kernel(const float* __restrict__ logits, int* __restrict__ outidx) {
    int row = blockIdx.x;
    const float* lr = logits + (size_t)row * kNE;
    int t = threadIdx.x;

    float lv[16], uu[16];
    float mx = -INFINITY, mn = INFINITY, umax = 0.0f;
    uint32_t base = (uint32_t)row * (uint32_t)kNE;
#pragma unroll
    for (int i = 0; i < 16; i++) {
        lv[i] = lr[i * 128 + t];
        mx = fmaxf(mx, lv[i]);
        mn = fminf(mn, lv[i]);
        uu[i] = uniform_at(base + (uint32_t)(i * 128 + t));
        umax = fmaxf(umax, uu[i]);
    }
    __shared__ float sMax[128], sMin[128], sU[128];
    sMax[t] = mx; sMin[t] = mn; sU[t] = umax;
    __syncthreads();
    for (int o = 64; o > 0; o >>= 1) {
        if (t < o) {
            sMax[t] = fmaxf(sMax[t], sMax[t + o]);
            sMin[t] = fminf(sMin[t], sMin[t + o]);
            sU[t]   = fmaxf(sU[t],   sU[t + o]);
        }
        __syncthreads();
    }
    float rowmax = sMax[0];
    float D = rowmax - sMin[0];
    float u_top = sU[0];
    __syncthreads();

    // threshold in u-space (conservative padding)
    float g_top = gumbel_of_u(u_top);
    float thr_g = g_top - D - 1e-4f;
    float u_req = expf(-expf(-thr_g)) * 0.9999f;

    float best = -INFINITY;
    int bi = kNE;
#pragma unroll
    for (int i = 0; i < 16; i++) {
        if (uu[i] >= u_req) {
            int e = i * 128 + t;
            float s = (lv[i] - rowmax) + gumbel_of_u(uu[i]);
            if (s > best || (s == best && e < bi)) { best = s; bi = e; }
        }
    }
    __shared__ float sBv[128];
    __shared__ int sBi[128];
    sBv[t] = best; sBi[t] = bi;
    __syncthreads();
    for (int o = 64; o > 0; o >>= 1) {
        if (t < o) {
            if (sBv[t + o] > sBv[t] || (sBv[t + o] == sBv[t] && sBi[t + o] < sBi[t])) {
                sBv[t] = sBv[t + o]; sBi[t] = sBi[t + o];
            }
        }
        __syncthreads();
    }
    if (t == 0) outidx[row] = sBi[0];
}

// ------------------------- loss partials: sum (E[idx]-cz)^2 -------------------------
__global__ void __launch_bounds__(256)
loss_kernel(const float* __restrict__ cz, const int* __restrict__ idx,
            const float* __restrict__ E, double* __restrict__ part) {
    double s = 0.0;
    size_t blockBase = (size_t)blockIdx.x * 4096;
#pragma unroll
    for (int i = 0; i < 16; i++) {
        size_t g = blockBase + (size_t)i * 256 + threadIdx.x;
        int rowr = (int)(g >> 8);
        int pos = (int)(g & 255);
        float d = E[(size_t)idx[rowr] * kE + pos] - cz[g];
        s += (double)d * d;
    }
    __shared__ double sd[256];
    sd[threadIdx.x] = s;
    __syncthreads();
    for (int o = 128; o > 0; o >>= 1) {
        if (threadIdx.x < o) sd[threadIdx.x] += sd[threadIdx.x + o];
        __syncthreads();
    }
    if (threadIdx.x == 0) part[blockIdx.x] = sd[0];
}

__global__ void loss_final_kernel(const double* __restrict__ part, float* __restrict__ out) {
    double s = 0.0;
    for (int i = threadIdx.x; i < 4096; i += 256) s += part[i];
    __shared__ double sd[256];
    sd[threadIdx.x] = s;
    __syncthreads();
    for (int o = 128; o > 0; o >>= 1) {
        if (threadIdx.x < o) sd[threadIdx.x] += sd[threadIdx.x + o];
        __syncthreads();
    }
    if (threadIdx.x == 0) {
        float m = (float)(sd[0] / 16777216.0);
        out[0] = m + 0.25f * m;
    }
}

// ------------------------- launch -------------------------
extern "C" void kernel_launch(void* const* d_in, const int* in_sizes, int n_in,
                              void* d_out, int out_size) {
    const float* z  = (const float*)d_in[0];
    const float* W0 = (const float*)d_in[1];
    const float* b0 = (const float*)d_in[2];
    const float* W1 = (const float*)d_in[3];
    const float* b1 = (const float*)d_in[4];
    const float* E  = (const float*)d_in[5];
    float* out = (float*)d_out;

    float *p_cz, *p_logits, *p_esq, *p_czsq, *p_P;
    int* p_idx;
    double* p_part;
    cudaGetSymbolAddress((void**)&p_cz, g_cz);
    cudaGetSymbolAddress((void**)&p_logits, g_logits);
    cudaGetSymbolAddress((void**)&p_esq, g_esq);
    cudaGetSymbolAddress((void**)&p_czsq, g_czsq);
    cudaGetSymbolAddress((void**)&p_idx, g_idx);
    cudaGetSymbolAddress((void**)&p_part, g_part);
    cudaGetSymbolAddress((void**)&p_P, g_P);

    // P = E @ W1 per channel (idx-independent)
    pgemm_kernel<<<dim3(kD / 128, kNE / 128, kCH), 256>>>(E, W1, p_P);
    // cz = z @ W0 + b0
    gemm0_kernel<<<dim3(kD / 128, kM1 / 128), 256>>>(z, W0, b0, p_cz, kD, kD);
    // row squared norms
    rowsq_kernel<<<kNE / 8, 256>>>(E, p_esq, kE / 4);
    rowsq_kernel<<<kMR / 8, 256>>>(p_cz, p_czsq, kE / 4);
    // logits
    dist_kernel<<<dim3(kNE / 128, kMR / 128), 256>>>(p_cz, E, p_czsq, p_esq, p_logits);
    // categorical sample
    argmax_kernel<<<kMR, 128>>>(p_logits, p_idx);

    int zoff = out_size - kM1 * kD;
    if (zoff >= 1) {
        loss_kernel<<<4096, 256>>>(p_cz, p_idx, E, p_part);
        loss_final_kernel<<<1, 256>>>(p_part, out);
    }
    if (out_size >= kM1 * kD) {
        float* zq = out + (zoff > 0 ? zoff : 0);
        gather_zq_kernel<<<kM1, 256>>>(p_P, p_idx, b1, zq);
    }
}